// round 1
// baseline (speedup 1.0000x reference)
#include <cuda_runtime.h>
#include <math.h>

#define BB 4
#define LL 2048
#define DD 32
#define TT 21   // NUM_TYPES + 1

// out layout (f32):
//   scores  : [B, L, L]   at offset 0                (16,777,216)
//   hidden  : [B, L, 2D]  at offset B*L*L            (   524,288)
//   t_diff  : [B, L, L]   at offset B*L*L + B*L*2D   (16,777,216)
#define SCORES_OFF  ((size_t)0)
#define HID_OFF     ((size_t)BB * LL * LL)
#define TD_OFF      (HID_OFF + (size_t)BB * LL * 2 * DD)

// 21x21 pairwise-type tables (index = type_i * 21 + type_j)
__device__ float g_gs[TT * TT];   // sigmoid(g) * softplus(s)
__device__ float g_dn[TT * TT];   // -softplus(d)   (natural-log domain, for __expf)

__global__ void tables_kernel(const float* __restrict__ type_table,
                              const float* __restrict__ w_g, const float* __restrict__ b_g,
                              const float* __restrict__ w_s, const float* __restrict__ b_s,
                              const float* __restrict__ w_d, const float* __restrict__ b_d)
{
    int idx = blockIdx.x * blockDim.x + threadIdx.x;
    if (idx >= TT * TT) return;
    int ti = idx / TT;
    int tj = idx - ti * TT;
    const float* ej = type_table + tj * DD;  // emb_j side: w[:D]
    const float* ei = type_table + ti * DD;  // emb_i side: w[D:]
    float g = *b_g, s = *b_s, d = *b_d;
#pragma unroll
    for (int k = 0; k < DD; k++) {
        float aj = ej[k], ai = ei[k];
        g = fmaf(aj, w_g[k], fmaf(ai, w_g[DD + k], g));
        s = fmaf(aj, w_s[k], fmaf(ai, w_s[DD + k], s));
        d = fmaf(aj, w_d[k], fmaf(ai, w_d[DD + k], d));
    }
    float sig = 1.0f / (1.0f + expf(-g));
    float sps = (s > 20.0f) ? s : log1pf(expf(s));
    float spd = (d > 20.0f) ? d : log1pf(expf(d));
    g_gs[idx] = sig * sps;
    g_dn[idx] = -spd;
}

// One block per (b, i) row. 256 threads; each thread handles 8 j's as 2x float4.
__global__ __launch_bounds__(256)
void row_kernel(const int*   __restrict__ event_type,
                const float* __restrict__ event_time,
                const float* __restrict__ Wt,
                const float* __restrict__ type_table,
                float* __restrict__ out)
{
    const int bi  = blockIdx.x;          // b * L + i
    const int b   = bi >> 11;            // / 2048
    const int i   = bi & (LL - 1);
    const int tid = threadIdx.x;

    __shared__ float sh_gs[TT];
    __shared__ float sh_dn[TT];

    const int   tyi = event_type[bi];    // broadcast load
    const float t_i = event_time[bi];    // broadcast load

    if (tid < TT) {
        int base = tyi * TT;
        sh_gs[tid] = g_gs[base + tid];
        sh_dn[tid] = g_dn[base + tid];
    }

    // fused hidden_vector row: threads 0..63 each compute one of the 2D outputs
    if (tid < 2 * DD) {
        float v;
        if (tid < DD) {
            int h = tid & 15;
            // div_term[h] = exp(2h * (-ln(1e4)/32)) = exp(h * -0.57564627...)
            float div = expf((float)h * -0.57564627324851142f);
            float arg = fmaf((float)i, div, t_i * Wt[h]);
            v = (tid < 16) ? sinf(arg) : cosf(arg);
        } else {
            v = type_table[tyi * DD + (tid - DD)];
        }
        out[HID_OFF + (size_t)bi * (2 * DD) + tid] = v;
    }
    __syncthreads();

    const float4* trow = (const float4*)(event_time + b * LL);
    const int4*   yrow = (const int4*)  (event_type + b * LL);
    float4* srow = (float4*)(out + SCORES_OFF + (size_t)bi * LL);
    float4* drow = (float4*)(out + TD_OFF     + (size_t)bi * LL);

#pragma unroll
    for (int c = 0; c < 2; c++) {
        const int v  = tid + c * 256;    // float4 index within the row
        const int j0 = v << 2;           // first j of this float4
        float4 tj = trow[v];
        int4   ty = yrow[v];

        float4 td, sd;

        {
            float ad = fabsf(tj.x - t_i);
            td.x = ad;
            sd.x = (j0 + 0 < i) ? sh_gs[ty.x] * __expf(sh_dn[ty.x] * ad) : 0.0f;
        }
        {
            float ad = fabsf(tj.y - t_i);
            td.y = ad;
            sd.y = (j0 + 1 < i) ? sh_gs[ty.y] * __expf(sh_dn[ty.y] * ad) : 0.0f;
        }
        {
            float ad = fabsf(tj.z - t_i);
            td.z = ad;
            sd.z = (j0 + 2 < i) ? sh_gs[ty.z] * __expf(sh_dn[ty.z] * ad) : 0.0f;
        }
        {
            float ad = fabsf(tj.w - t_i);
            td.w = ad;
            sd.w = (j0 + 3 < i) ? sh_gs[ty.w] * __expf(sh_dn[ty.w] * ad) : 0.0f;
        }

        srow[v] = sd;
        drow[v] = td;
    }
}

extern "C" void kernel_launch(void* const* d_in, const int* in_sizes, int n_in,
                              void* d_out, int out_size)
{
    const int*   event_type = (const int*)  d_in[0];
    const float* event_time = (const float*)d_in[1];
    const float* Wt         = (const float*)d_in[2];
    const float* type_table = (const float*)d_in[3];
    const float* w_g        = (const float*)d_in[4];
    const float* b_g        = (const float*)d_in[5];
    const float* w_s        = (const float*)d_in[6];
    const float* b_s        = (const float*)d_in[7];
    const float* w_d        = (const float*)d_in[8];
    const float* b_d        = (const float*)d_in[9];
    float* out = (float*)d_out;

    tables_kernel<<<1, 512>>>(type_table, w_g, b_g, w_s, b_s, w_d, b_d);
    row_kernel<<<BB * LL, 256>>>(event_type, event_time, Wt, type_table, out);
}